// round 16
// baseline (speedup 1.0000x reference)
#include <cuda_runtime.h>
#include <cuda_fp16.h>
#include <cstdint>

// ---------------- problem constants ----------------
#define N_TOK   262144
#define TOPK    2
#define NSLOTS  (N_TOK * TOPK)     // 524288
#define D       128
#define NEXP    8
#define TS      128                // slots per tile
#define MAXTILES (NSLOTS / TS + NEXP)   // 4104

// ---------------- device scratch ----------------
__device__ uint4 g_whp[NEXP * 2048];             // W fp16, packed + out-col permuted (32KB/expert)
__device__ int   g_seg[NEXP + 1];
__device__ int   g_tile_e[MAXTILES];
__device__ int   g_tile_s[MAXTILES];
__device__ int   g_ntiles;

// ---------------- helpers ----------------
__device__ __forceinline__ uint32_t smem_u32(const void* p) {
    uint32_t a;
    asm("{ .reg .u64 t; cvta.to.shared.u64 t, %1; cvt.u32.u64 %0, t; }" : "=r"(a) : "l"(p));
    return a;
}
__device__ __forceinline__ void ldsm_x4(uint32_t* r, uint32_t addr) {
    asm volatile("ldmatrix.sync.aligned.m8n8.x4.shared.b16 {%0,%1,%2,%3}, [%4];"
        : "=r"(r[0]), "=r"(r[1]), "=r"(r[2]), "=r"(r[3]) : "r"(addr));
}
__device__ __forceinline__ void mma_fp16(float* c, const uint32_t* a, uint32_t b0, uint32_t b1) {
    asm volatile("mma.sync.aligned.m16n8k16.row.col.f32.f16.f16.f32 "
        "{%0,%1,%2,%3}, {%4,%5,%6,%7}, {%8,%9}, {%0,%1,%2,%3};"
        : "+f"(c[0]), "+f"(c[1]), "+f"(c[2]), "+f"(c[3])
        : "r"(a[0]), "r"(a[1]), "r"(a[2]), "r"(a[3]), "r"(b0), "r"(b1));
}
#define RED_ADD_V4(ptr, a, b, c, d) \
    asm volatile("red.global.add.v4.f32 [%0], {%1, %2, %3, %4};" \
        :: "l"(ptr), "f"(a), "f"(b), "f"(c), "f"(d) : "memory")

__device__ __forceinline__ uint32_t f2h2(float lo, float hi) {
    __half2 h = __floats2half2_rn(lo, hi);
    return *reinterpret_cast<uint32_t*>(&h);
}

// convert 8 fp32 -> fp16 (16 B)
__device__ __forceinline__ uint4 cvt8h(const float* v) {
    uint32_t hu[4];
#pragma unroll
    for (int i = 0; i < 4; i++) {
        __half2 hp = __floats2half2_rn(v[2 * i], v[2 * i + 1]);
        hu[i] = *reinterpret_cast<uint32_t*>(&hp);
    }
    return make_uint4(hu[0], hu[1], hu[2], hu[3]);
}

// -------------------------------------------------------------------
// Prologue 1: weight fp32 [E, d_out, d_in] -> packed fp16, out-col permuted.
// Image row c = f*8 + p  (f: n16-frag 0..15, p: col-in-frag 0..7)
// holds actual out o = (p>>1)*32 + f*2 + (p&1)   [bijective on 0..127]
// Inverse (used here): q=o>>5, rem=o&31, f=rem>>1, r=rem&1, p=q*2+r, c=f*8+p.
// grid = NEXP*8, block = 256 (16 rows x 16 uint4-chunks per block)
// -------------------------------------------------------------------
__global__ void wconv_kernel(const float* __restrict__ w) {
    int blk = blockIdx.x;
    int e = blk >> 3;
    int o = (blk & 7) * 16 + (threadIdx.x >> 4);     // actual out row 0..127
    int w16 = threadIdx.x & 15;                      // uint4 chunk within row
    const float* wr = w + ((size_t)e * D + o) * D + w16 * 8;
    float v[8];
#pragma unroll
    for (int i = 0; i < 8; i++) v[i] = wr[i];
    int q = o >> 5, rem = o & 31;
    int fფ = rem >> 1, r = rem & 1;
    int p = q * 2 + r;
    int c = fფ * 8 + p;                              // permuted image row
    g_whp[e * 2048 + c * 16 + w16] = cvt8h(v);
}

// -------------------------------------------------------------------
// Prologue 2: expert segments + dense tile map
// -------------------------------------------------------------------
__global__ void seg_kernel(const int* __restrict__ sei) {
    __shared__ int seg[NEXP + 1];
    __shared__ int cnts[NEXP];
    int t = threadIdx.x;
    if (t <= NEXP) {
        int lo = 0, hi = NSLOTS;
        while (lo < hi) {
            int mid = (lo + hi) >> 1;
            if (sei[mid] < t) lo = mid + 1; else hi = mid;
        }
        seg[t] = lo;
        g_seg[t] = lo;
    }
    __syncthreads();
    if (t < NEXP) cnts[t] = (seg[t + 1] - seg[t] + TS - 1) / TS;
    __syncthreads();
    if (t < NEXP) {
        int off = 0;
        for (int i = 0; i < t; i++) off += cnts[i];
        int s = seg[t];
        for (int i = 0; i < cnts[t]; i++) {
            g_tile_e[off + i] = t;
            g_tile_s[off + i] = s + i * TS;
        }
    }
    if (t == 0) {
        int tot = 0;
        for (int i = 0; i < NEXP; i++) tot += cnts[i];
        g_ntiles = tot;
    }
}

// -------------------------------------------------------------------
// Prologue 3: zero-init out (atomic accumulation target)
// -------------------------------------------------------------------
__global__ void zero_kernel(float4* __restrict__ out) {
    size_t idx = (size_t)blockIdx.x * blockDim.x + threadIdx.x;
    out[idx] = make_float4(0.f, 0.f, 0.f, 0.f);
}

// -------------------------------------------------------------------
// SMEM layout: W image only (35 KB)
// -------------------------------------------------------------------
#define XROWB 272
#define IMGB  (128 * XROWB)          // 34816
#define OFF_WH 0
#define SMEM_TOTAL IMGB

// -------------------------------------------------------------------
// Main: barrier-free streaming — warp tile 16x128 (A loaded ONCE),
//       A direct from GMEM, B via LDSM, epilogue = aligned RED.v4
// -------------------------------------------------------------------
extern "C" __global__ void __launch_bounds__(256, 2)
moe_mma_kernel(const float* __restrict__ x,
               const float* __restrict__ gates,
               const int*   __restrict__ ssi,
               float* __restrict__ out) {
    int ntiles = g_ntiles;
    int nc = gridDim.x;
    int per = ntiles / nc, rem = ntiles % nc;
    int t0 = blockIdx.x * per + min((int)blockIdx.x, rem);
    int t1 = t0 + per + (blockIdx.x < rem ? 1 : 0);
    if (t0 >= t1) return;

    extern __shared__ char smem[];
    uint32_t sb = smem_u32(smem);

    int tid = threadIdx.x;
    int wid = tid >> 5;               // warp covers rows wid*16..+15, ALL 128 outs
    int lane = tid & 31;

    int row_lo = lane >> 2;           // 0..7: fragment row within m8
    int c0 = (lane & 3) * 2;          // k-pair base within k16 chunk (A side)
    int colq = (lane & 3) * 32;       // epilogue: 32 consecutive out cols
    int lrow = (lane & 7) | (lane & 8);
    int kby  = (lane >> 4) * 16;
    uint32_t aB = sb + OFF_WH + (uint32_t)lrow * XROWB + kby;

    // ---- prime tile t0 metadata (2 rows/thread: +0, +8) ----
    int e  = g_tile_e[t0];
    int s0 = g_tile_s[t0];
    int cnt = min(TS, g_seg[e + 1] - s0);
    int f[2]; float gv[2];
#pragma unroll
    for (int i = 0; i < 2; i++) {
        int j = wid * 16 + row_lo + i * 8;
        bool ok = j < cnt;
        f[i]  = ok ? ssi[s0 + j] : 0;
        gv[i] = ok ? gates[f[i]] : 0.f;
    }

    int staged_e = -1;

    for (int t = t0; t < t1; t++) {
        // ---- stage W on expert change (CTA-uniform branch, rare) ----
        if (e != staged_e) {
            __syncthreads();           // all warps done with old image
            const uint4* whe = g_whp + e * 2048;
#pragma unroll
            for (int i = 0; i < 8; i++) {
                int cid = tid + 256 * i;
                int row = cid >> 4;
                int w16 = cid & 15;
                *(uint4*)(smem + OFF_WH + row * XROWB + w16 * 16) = whe[cid];
            }
            staged_e = e;
            __syncthreads();           // new image visible
        }

        // row base pointers for this tile
        const float* xr0 = x + (size_t)(f[0] >> 1) * D;
        const float* xr1 = x + (size_t)(f[1] >> 1) * D;

        // ---- prefetch metadata for t+1 (hidden under MMA) ----
        bool havenext = (t + 1 < t1);
        int en = e, s0n = s0, cntn = cnt;
        int nf[2]; float ngv[2];
        if (havenext) {
            en  = g_tile_e[t + 1];
            s0n = g_tile_s[t + 1];
            cntn = min(TS, g_seg[en + 1] - s0n);
#pragma unroll
            for (int i = 0; i < 2; i++) {
                int j = wid * 16 + row_lo + i * 8;
                bool ok = j < cntn;
                nf[i]  = ok ? ssi[s0n + j] : 0;
                ngv[i] = ok ? gates[nf[i]] : 0.f;
            }
        } else {
#pragma unroll
            for (int i = 0; i < 2; i++) { nf[i] = 0; ngv[i] = 0.f; }
        }

        // ---- MMA: A direct from GMEM (4 LDG.64/kk), B via LDSM ----
        // acc[frag 0..15][4]: [0..1] row_lo cols 2f,2f+1 ; [2..3] row_lo+8
        float acc[16][4];
#pragma unroll
        for (int nt = 0; nt < 16; nt++)
#pragma unroll
            for (int i = 0; i < 4; i++) acc[nt][i] = 0.f;

#pragma unroll
        for (int kk = 0; kk < 8; kk++) {
            int kb = kk * 16;
            float2 u0 = *(const float2*)(xr0 + kb + c0);
            float2 u1 = *(const float2*)(xr1 + kb + c0);
            float2 u2 = *(const float2*)(xr0 + kb + c0 + 8);
            float2 u3 = *(const float2*)(xr1 + kb + c0 + 8);
            uint32_t a[4];
            a[0] = f2h2(u0.x, u0.y);
            a[1] = f2h2(u1.x, u1.y);
            a[2] = f2h2(u2.x, u2.y);
            a[3] = f2h2(u3.x, u3.y);
#pragma unroll
            for (int g = 0; g < 8; g++) {
                uint32_t bh[4];
                ldsm_x4(bh, aB + g * 16 * XROWB + kk * 32);
                mma_fp16(acc[2 * g],     a, bh[0], bh[2]);
                mma_fp16(acc[2 * g + 1], a, bh[1], bh[3]);
            }
        }

        // ---- fused epilogue: thread owns 32 consecutive out cols/row ----
        {
#pragma unroll
            for (int i = 0; i < 2; i++) {
                int j = wid * 16 + row_lo + i * 8;
                if (j < cnt) {
                    float g = gv[i];
                    float* dp = out + (size_t)(f[i] >> 1) * D + colq;
                    int lo = i * 2;     // acc component offset for this row
#pragma unroll
                    for (int u = 0; u < 8; u++) {
                        RED_ADD_V4(dp + 4 * u,
                                   acc[2 * u][lo] * g,     acc[2 * u][lo + 1] * g,
                                   acc[2 * u + 1][lo] * g, acc[2 * u + 1][lo + 1] * g);
                    }
                }
            }
        }

        // rotate tile state
        e = en; s0 = s0n; cnt = cntn;
#pragma unroll
        for (int i = 0; i < 2; i++) { f[i] = nf[i]; gv[i] = ngv[i]; }
    }
}

// -------------------------------------------------------------------
extern "C" void kernel_launch(void* const* d_in, const int* in_sizes, int n_in,
                              void* d_out, int out_size) {
    const float* inputs = (const float*)d_in[0];
    const float* weight = (const float*)d_in[1];
    const float* gates  = (const float*)d_in[2];
    const int*   sei    = (const int*)d_in[4];
    const int*   ssi    = (const int*)d_in[5];
    float* out = (float*)d_out;

    int nsm = 148;
    cudaDeviceGetAttribute(&nsm, cudaDevAttrMultiProcessorCount, 0);

    cudaFuncSetAttribute(moe_mma_kernel,
                         cudaFuncAttributeMaxDynamicSharedMemorySize, SMEM_TOTAL);

    wconv_kernel<<<NEXP * 8, 256>>>(weight);
    seg_kernel<<<1, 32>>>(sei);
    zero_kernel<<<(N_TOK * D / 4) / 256, 256>>>((float4*)out);

    moe_mma_kernel<<<2 * nsm, 256, SMEM_TOTAL>>>(inputs, gates, ssi, out);
}

// round 17
// speedup vs baseline: 1.1015x; 1.1015x over previous
#include <cuda_runtime.h>
#include <cuda_fp16.h>
#include <cstdint>

// ---------------- problem constants ----------------
#define N_TOK   262144
#define TOPK    2
#define NSLOTS  (N_TOK * TOPK)     // 524288
#define D       128
#define NEXP    8
#define TS      128                // slots per tile
#define MAXTILES (NSLOTS / TS + NEXP)   // 4104

// ---------------- device scratch ----------------
__device__ uint4 g_whp[NEXP * 2048];             // W fp16, packed + out-col permuted (32KB/expert)
__device__ int   g_seg[NEXP + 1];
__device__ int   g_tile_e[MAXTILES];
__device__ int   g_tile_s[MAXTILES];
__device__ int   g_ntiles;

// ---------------- helpers ----------------
__device__ __forceinline__ uint32_t smem_u32(const void* p) {
    uint32_t a;
    asm("{ .reg .u64 t; cvta.to.shared.u64 t, %1; cvt.u32.u64 %0, t; }" : "=r"(a) : "l"(p));
    return a;
}
__device__ __forceinline__ void ldsm_x4(uint32_t* r, uint32_t addr) {
    asm volatile("ldmatrix.sync.aligned.m8n8.x4.shared.b16 {%0,%1,%2,%3}, [%4];"
        : "=r"(r[0]), "=r"(r[1]), "=r"(r[2]), "=r"(r[3]) : "r"(addr));
}
__device__ __forceinline__ void mma_fp16(float* c, const uint32_t* a, uint32_t b0, uint32_t b1) {
    asm volatile("mma.sync.aligned.m16n8k16.row.col.f32.f16.f16.f32 "
        "{%0,%1,%2,%3}, {%4,%5,%6,%7}, {%8,%9}, {%0,%1,%2,%3};"
        : "+f"(c[0]), "+f"(c[1]), "+f"(c[2]), "+f"(c[3])
        : "r"(a[0]), "r"(a[1]), "r"(a[2]), "r"(a[3]), "r"(b0), "r"(b1));
}
#define RED_ADD_V4(ptr, a, b, c, d) \
    asm volatile("red.global.add.v4.f32 [%0], {%1, %2, %3, %4};" \
        :: "l"(ptr), "f"(a), "f"(b), "f"(c), "f"(d) : "memory")
#define PREFETCH_L1(ptr) \
    asm volatile("prefetch.global.L1 [%0];" :: "l"(ptr))

__device__ __forceinline__ uint32_t f2h2(float lo, float hi) {
    __half2 h = __floats2half2_rn(lo, hi);
    return *reinterpret_cast<uint32_t*>(&h);
}

// convert 8 fp32 -> fp16 (16 B)
__device__ __forceinline__ uint4 cvt8h(const float* v) {
    uint32_t hu[4];
#pragma unroll
    for (int i = 0; i < 4; i++) {
        __half2 hp = __floats2half2_rn(v[2 * i], v[2 * i + 1]);
        hu[i] = *reinterpret_cast<uint32_t*>(&hp);
    }
    return make_uint4(hu[0], hu[1], hu[2], hu[3]);
}

// -------------------------------------------------------------------
// Fused prologue:
//   blocks [0, 64)    : wconv — W fp32 -> packed fp16, out-col permuted
//   block  64         : seg   — expert segments + tile map
//   blocks [65, ...)  : zero  — zero-init out
// Permutation (within each 64-col half, as in R15):
//   image row c = half*64 + nt*8 + 2q + r  holds out o = half*64 + q*16 + nt*2 + r
// -------------------------------------------------------------------
__global__ void prologue_kernel(const float* __restrict__ w,
                                const int* __restrict__ sei,
                                float4* __restrict__ out) {
    int blk = blockIdx.x;
    if (blk < 64) {
        // ---- wconv ----
        int e = blk >> 3;
        int row = (blk & 7) * 16 + (threadIdx.x >> 4);   // actual out row 0..127
        int w16 = threadIdx.x & 15;                      // uint4 chunk within row
        const float* wr = w + ((size_t)e * D + row) * D + w16 * 8;
        float v[8];
#pragma unroll
        for (int i = 0; i < 8; i++) v[i] = wr[i];
        int half = row >> 6, oloc = row & 63;
        int q = oloc >> 4, wl = oloc & 15;
        int nt = wl >> 1, r = wl & 1;
        int c = half * 64 + nt * 8 + 2 * q + r;          // permuted image row
        g_whp[e * 2048 + c * 16 + w16] = cvt8h(v);
    } else if (blk == 64) {
        // ---- seg ----
        __shared__ int seg[NEXP + 1];
        __shared__ int cnts[NEXP];
        int t = threadIdx.x;
        if (t <= NEXP) {
            int lo = 0, hi = NSLOTS;
            while (lo < hi) {
                int mid = (lo + hi) >> 1;
                if (sei[mid] < t) lo = mid + 1; else hi = mid;
            }
            seg[t] = lo;
            g_seg[t] = lo;
        }
        __syncthreads();
        if (t < NEXP) cnts[t] = (seg[t + 1] - seg[t] + TS - 1) / TS;
        __syncthreads();
        if (t < NEXP) {
            int off = 0;
            for (int i = 0; i < t; i++) off += cnts[i];
            int s = seg[t];
            for (int i = 0; i < cnts[t]; i++) {
                g_tile_e[off + i] = t;
                g_tile_s[off + i] = s + i * TS;
            }
        }
        if (t == 0) {
            int tot = 0;
            for (int i = 0; i < NEXP; i++) tot += cnts[i];
            g_ntiles = tot;
        }
    } else {
        // ---- zero ----
        size_t idx = (size_t)(blk - 65) * blockDim.x + threadIdx.x;
        out[idx] = make_float4(0.f, 0.f, 0.f, 0.f);
    }
}

// -------------------------------------------------------------------
// SMEM layout: W image only (35 KB)
// -------------------------------------------------------------------
#define XROWB 272
#define IMGB  (128 * XROWB)          // 34816
#define OFF_WH 0
#define SMEM_TOTAL IMGB

// -------------------------------------------------------------------
// Main: barrier-free streaming — A direct from GMEM (L1-prefetched),
//       B via LDSM, epilogue = aligned RED.v4
// -------------------------------------------------------------------
extern "C" __global__ void __launch_bounds__(256, 2)
moe_mma_kernel(const float* __restrict__ x,
               const float* __restrict__ gates,
               const int*   __restrict__ ssi,
               float* __restrict__ out) {
    int ntiles = g_ntiles;
    int nc = gridDim.x;
    int per = ntiles / nc, rem = ntiles % nc;
    int t0 = blockIdx.x * per + min((int)blockIdx.x, rem);
    int t1 = t0 + per + (blockIdx.x < rem ? 1 : 0);
    if (t0 >= t1) return;

    extern __shared__ char smem[];
    uint32_t sb = smem_u32(smem);

    int tid = threadIdx.x;
    int wid = tid >> 5;
    int lane = tid & 31;

    // warp tiles: wr 0..3 (32 slots), wc 0..1 (64 outs)
    int wr = wid & 3;
    int wc = wid >> 2;
    int row_lo = lane >> 2;           // fragment row within m8
    int c0 = (lane & 3) * 2;          // k-pair base within k16 chunk (A side)
    int lrow = (lane & 7) | (lane & 8);
    int kby  = (lane >> 4) * 16;
    uint32_t aB = sb + OFF_WH + (uint32_t)(wc * 64 + lrow) * XROWB + kby;

    // ---- prime tile t0 metadata (4 rows/thread: +0,+8,+16,+24) ----
    int e  = g_tile_e[t0];
    int s0 = g_tile_s[t0];
    int cnt = min(TS, g_seg[e + 1] - s0);
    int f[4]; float gv[4];
#pragma unroll
    for (int i = 0; i < 4; i++) {
        int j = wr * 32 + row_lo + i * 8;
        bool ok = j < cnt;
        f[i]  = ok ? ssi[s0 + j] : 0;
        gv[i] = ok ? gates[f[i]] : 0.f;
    }
    // prefetch t0's rows into L1 (wc==0 warps; quad covers the 4 lines)
    if (wc == 0) {
        int q = lane & 3;
#pragma unroll
        for (int i = 0; i < 4; i++)
            PREFETCH_L1((const char*)x + (size_t)(f[i] >> 1) * 512 + q * 128);
    }

    int staged_e = -1;

    for (int t = t0; t < t1; t++) {
        // ---- stage W on expert change (CTA-uniform branch, rare) ----
        if (e != staged_e) {
            __syncthreads();           // all warps done with old image
            const uint4* whe = g_whp + e * 2048;
#pragma unroll
            for (int i = 0; i < 8; i++) {
                int cid = tid + 256 * i;
                int row = cid >> 4;
                int w16 = cid & 15;
                *(uint4*)(smem + OFF_WH + row * XROWB + w16 * 16) = whe[cid];
            }
            staged_e = e;
            __syncthreads();           // new image visible
        }

        // row base pointers for this tile
        const float* xr[4];
#pragma unroll
        for (int i = 0; i < 4; i++) xr[i] = x + (size_t)(f[i] >> 1) * D;

        // ---- prefetch metadata for t+1 + L1-prefetch its X rows ----
        bool havenext = (t + 1 < t1);
        int en = e, s0n = s0, cntn = cnt;
        int nf[4]; float ngv[4];
        if (havenext) {
            en  = g_tile_e[t + 1];
            s0n = g_tile_s[t + 1];
            cntn = min(TS, g_seg[en + 1] - s0n);
#pragma unroll
            for (int i = 0; i < 4; i++) {
                int j = wr * 32 + row_lo + i * 8;
                bool ok = j < cntn;
                nf[i]  = ok ? ssi[s0n + j] : 0;
                ngv[i] = ok ? gates[nf[i]] : 0.f;
            }
            if (wc == 0) {
                int q = lane & 3;
#pragma unroll
                for (int i = 0; i < 4; i++)
                    PREFETCH_L1((const char*)x + (size_t)(nf[i] >> 1) * 512 + q * 128);
            }
        } else {
#pragma unroll
            for (int i = 0; i < 4; i++) { nf[i] = 0; ngv[i] = 0.f; }
        }

        // ---- MMA: A direct from GMEM (L1-hot), B via LDSM ----
        float acc[2][8][4];
#pragma unroll
        for (int mt = 0; mt < 2; mt++)
#pragma unroll
            for (int nt = 0; nt < 8; nt++)
#pragma unroll
                for (int i = 0; i < 4; i++) acc[mt][nt][i] = 0.f;

#pragma unroll
        for (int kk = 0; kk < 8; kk++) {
            int kb = kk * 16;
            uint32_t a[2][4];
#pragma unroll
            for (int mt = 0; mt < 2; mt++) {
                float2 u0 = *(const float2*)(xr[2 * mt]     + kb + c0);
                float2 u1 = *(const float2*)(xr[2 * mt + 1] + kb + c0);
                float2 u2 = *(const float2*)(xr[2 * mt]     + kb + c0 + 8);
                float2 u3 = *(const float2*)(xr[2 * mt + 1] + kb + c0 + 8);
                a[mt][0] = f2h2(u0.x, u0.y);
                a[mt][1] = f2h2(u1.x, u1.y);
                a[mt][2] = f2h2(u2.x, u2.y);
                a[mt][3] = f2h2(u3.x, u3.y);
            }
#pragma unroll
            for (int ng = 0; ng < 4; ng++) {
                uint32_t bh[4];
                ldsm_x4(bh, aB + ng * 16 * XROWB + kk * 32);
#pragma unroll
                for (int mt = 0; mt < 2; mt++) {
                    mma_fp16(acc[mt][2 * ng],     a[mt], bh[0], bh[2]);
                    mma_fp16(acc[mt][2 * ng + 1], a[mt], bh[1], bh[3]);
                }
            }
        }

        // ---- fused epilogue: thread owns 16 consecutive out cols/row ----
        {
            int colb = wc * 64 + (lane & 3) * 16;
#pragma unroll
            for (int mt = 0; mt < 2; mt++) {
                int ia = 2 * mt, ib = 2 * mt + 1;
                int ja = wr * 32 + row_lo + ia * 8;
                int jb = wr * 32 + row_lo + ib * 8;
                bool oka = ja < cnt, okb = jb < cnt;
                float ga = gv[ia], gb = gv[ib];
                float* da = out + (size_t)(f[ia] >> 1) * D + colb;
                float* db = out + (size_t)(f[ib] >> 1) * D + colb;
#pragma unroll
                for (int u = 0; u < 4; u++) {
                    if (oka)
                        RED_ADD_V4(da + 4 * u,
                                   acc[mt][2 * u][0] * ga, acc[mt][2 * u][1] * ga,
                                   acc[mt][2 * u + 1][0] * ga, acc[mt][2 * u + 1][1] * ga);
                    if (okb)
                        RED_ADD_V4(db + 4 * u,
                                   acc[mt][2 * u][2] * gb, acc[mt][2 * u][3] * gb,
                                   acc[mt][2 * u + 1][2] * gb, acc[mt][2 * u + 1][3] * gb);
                }
            }
        }

        // rotate tile state
        e = en; s0 = s0n; cnt = cntn;
#pragma unroll
        for (int i = 0; i < 4; i++) { f[i] = nf[i]; gv[i] = ngv[i]; }
    }
}

// -------------------------------------------------------------------
extern "C" void kernel_launch(void* const* d_in, const int* in_sizes, int n_in,
                              void* d_out, int out_size) {
    const float* inputs = (const float*)d_in[0];
    const float* weight = (const float*)d_in[1];
    const float* gates  = (const float*)d_in[2];
    const int*   sei    = (const int*)d_in[4];
    const int*   ssi    = (const int*)d_in[5];
    float* out = (float*)d_out;

    int nsm = 148;
    cudaDeviceGetAttribute(&nsm, cudaDevAttrMultiProcessorCount, 0);

    cudaFuncSetAttribute(moe_mma_kernel,
                         cudaFuncAttributeMaxDynamicSharedMemorySize, SMEM_TOTAL);

    // fused prologue: wconv (64 blocks) + seg (1) + zero (N_TOK*D/4/256)
    int zero_blocks = (N_TOK * D / 4) / 256;
    prologue_kernel<<<65 + zero_blocks, 256>>>(weight, sei, (float4*)out);

    moe_mma_kernel<<<2 * nsm, 256, SMEM_TOTAL>>>(inputs, gates, ssi, out);
}